// round 6
// baseline (speedup 1.0000x reference)
#include <cuda_runtime.h>
#include <cuda_fp16.h>
#include <math.h>

#define N_NODES 50000
#define DEG     16
#define WIDTH   256
#define BATCH   8192
#define EPS     1e-12f
#define NREF    (BATCH * DEG)             // 131072 neighbor consumer refs
#define SCANB   ((N_NODES + 1023) / 1024) // 49
#define AGGB_BYTES (BATCH * WIDTH * 2)    // 4,194,304 = d_out region1 size

// ---- device globals: ~0.93MB TOTAL (big scratch lives in d_out) ----
__device__ int      g_owner[N_NODES];     // 200KB last batch writer (-1 none)
__device__ int      g_roff [N_NODES + 1]; // 200KB reverse-adjacency offsets
__device__ int      g_rlist[NREF];        // 524KB consumer batch-row ids
__device__ int      g_bsum [64];
__device__ int      g_boff [64];
__device__ unsigned g_barCount;           // manual grid barrier (self-resetting)
__device__ unsigned g_barPhase;

// ---------------------------------------------------------------------------
// setup: owner map + reverse-adjacency CSR (cnt/cursor borrows d_out region1)
// ---------------------------------------------------------------------------
__global__ void init_kernel(int* __restrict__ cnt) {
    int i = blockIdx.x * 256 + threadIdx.x;
    if (i < N_NODES) { g_owner[i] = -1; cnt[i] = 0; }
}

__global__ void owner_scatter_kernel(const int* __restrict__ node_idx) {
    int i = blockIdx.x * 256 + threadIdx.x;
    if (i < BATCH) atomicMax(&g_owner[node_idx[i]], i);  // last-wins on dups
}

__global__ void count_refs_kernel(const int* __restrict__ node_idx,
                                  const int* __restrict__ nbd,
                                  int* __restrict__ cnt) {
    int t = blockIdx.x * 256 + threadIdx.x;
    if (t >= NREF) return;
    int i = t >> 4, d = t & 15;
    int n = __ldg(&nbd[__ldg(&node_idx[i]) * DEG + d]);
    atomicAdd(&cnt[n], 1);
}

__global__ void scanA_kernel(const int* __restrict__ cnt) {
    __shared__ int s[1024];
    int b = blockIdx.x, t = threadIdx.x, idx = b * 1024 + t;
    int x = (idx < N_NODES) ? cnt[idx] : 0;
    s[t] = x;
    __syncthreads();
#pragma unroll
    for (int off = 1; off < 1024; off <<= 1) {
        int v = (t >= off) ? s[t - off] : 0;
        __syncthreads();
        s[t] += v;
        __syncthreads();
    }
    if (idx < N_NODES) g_roff[idx] = s[t] - x;
    if (t == 1023) g_bsum[b] = s[1023];
}

__global__ void scanB_kernel() {
    __shared__ int s[64];
    int t = threadIdx.x;
    int x = (t < SCANB) ? g_bsum[t] : 0;
    s[t] = x;
    __syncthreads();
#pragma unroll
    for (int off = 1; off < 64; off <<= 1) {
        int v = (t >= off) ? s[t - off] : 0;
        __syncthreads();
        s[t] += v;
        __syncthreads();
    }
    if (t < SCANB) g_boff[t] = s[t] - x;
}

__global__ void scanC_kernel(int* __restrict__ cursor) {
    int b = blockIdx.x, t = threadIdx.x, idx = b * 1024 + t;
    if (idx < N_NODES) {
        int v = g_roff[idx] + g_boff[b];
        g_roff[idx] = v;
        cursor[idx] = v;
    }
    if (b == 0 && t == 0) g_roff[N_NODES] = NREF;
}

__global__ void fill_refs_kernel(const int* __restrict__ node_idx,
                                 const int* __restrict__ nbd,
                                 int* __restrict__ cursor) {
    int t = blockIdx.x * 256 + threadIdx.x;
    if (t >= NREF) return;
    int i = t >> 4, d = t & 15;
    int n = __ldg(&nbd[__ldg(&node_idx[i]) * DEG + d]);
    int p = atomicAdd(&cursor[n], 1);
    g_rlist[p] = i;
}

__global__ void zero_nm2_kernel(float4* __restrict__ nm2) {
    int t = blockIdx.x * 256 + threadIdx.x;
    if (t < (BATCH * 128) / 4)   // 4.19MB of packed half2 words
        nm2[t] = make_float4(0.f, 0.f, 0.f, 0.f);
}

// ---------------------------------------------------------------------------
// aggb GEMM: aggb[i,:] = relu(feats[i,:] @ W_agg + b_agg), fp16 out
//   BM=64 BN=256 BK=32, block(32,16)=512thr, 4x8 microtile
// ---------------------------------------------------------------------------
__global__ __launch_bounds__(512, 1)
void aggb_gemm_kernel(const float* __restrict__ A, const float* __restrict__ B,
                      const float* __restrict__ bias, __half* __restrict__ C) {
    __shared__ float As[32][68];
    __shared__ float Bs[32][256];
    const int tx = threadIdx.x, ty = threadIdx.y;
    const int tid = ty * 32 + tx;
    const int rowBase = blockIdx.x * 64;
    const int lr = tid >> 3, lk4 = tid & 7;
    const int bk = tid >> 6, bc4 = tid & 63;

    float acc[4][8];
#pragma unroll
    for (int i = 0; i < 4; ++i)
#pragma unroll
        for (int j = 0; j < 8; ++j) acc[i][j] = 0.f;

#pragma unroll 1
    for (int t = 0; t < 8; ++t) {
        const int kbase = t * 32;
        {
            float4 v = *(const float4*)&A[(rowBase + lr) * 256 + kbase + lk4 * 4];
            As[lk4 * 4 + 0][lr] = v.x;
            As[lk4 * 4 + 1][lr] = v.y;
            As[lk4 * 4 + 2][lr] = v.z;
            As[lk4 * 4 + 3][lr] = v.w;
        }
#pragma unroll
        for (int p = 0; p < 4; ++p) {
            int kk = bk + p * 8;
            *(float4*)&Bs[kk][bc4 * 4] = *(const float4*)&B[(kbase + kk) * 256 + bc4 * 4];
        }
        __syncthreads();
#pragma unroll
        for (int kk = 0; kk < 32; ++kk) {
            float4 av = *(const float4*)&As[kk][ty * 4];
            float a[4] = {av.x, av.y, av.z, av.w};
            float b[8];
#pragma unroll
            for (int j = 0; j < 8; ++j) b[j] = Bs[kk][tx + 32 * j];
#pragma unroll
            for (int i = 0; i < 4; ++i)
#pragma unroll
                for (int j = 0; j < 8; ++j) acc[i][j] = fmaf(a[i], b[j], acc[i][j]);
        }
        __syncthreads();
    }

    float bv[8];
#pragma unroll
    for (int j = 0; j < 8; ++j) bv[j] = __ldg(&bias[tx + 32 * j]);
#pragma unroll
    for (int i = 0; i < 4; ++i) {
        int r = rowBase + ty * 4 + i;
#pragma unroll
        for (int j = 0; j < 8; ++j)
            C[r * 256 + tx + 32 * j] = __float2half_rn(fmaxf(acc[i][j] + bv[j], 0.f));
    }
}

// ---------------------------------------------------------------------------
// packed-half2 componentwise atomic max (values >= 0, monotone)
// ---------------------------------------------------------------------------
__device__ __forceinline__ void atomic_max_half2(unsigned* p, unsigned vbits) {
    if (vbits == 0u) return;           // max with (0,0) is identity (all >= 0)
    unsigned old = *p;
    while (true) {
        __half2 cur = *reinterpret_cast<__half2*>(&old);
        __half2 vv  = *reinterpret_cast<__half2*>(&vbits);
        __half2 mx  = __hmax2(cur, vv);
        unsigned mxb = *reinterpret_cast<unsigned*>(&mx);
        if (mxb == old) return;
        unsigned got = atomicCAS(p, old, mxb);
        if (got == old) return;
        old = got;
    }
}

// ---------------------------------------------------------------------------
// sweep: per 64-node tile:
//   phase C: H1 = normalize(relu([H0 | nm1(aggb fp16)] @ W0 + b0)) -> smem
//   phase D: agg2 = relu(H1 @ W_agg + b_agg) -> stage fp16 -> CSR CAS-max nm2
// ---------------------------------------------------------------------------
#define SWEEP_SMEM ((32*68 + 32*256 + 256*65 + 256) * 4 + 64*DEG * 4)  // 113152

__global__ __launch_bounds__(512, 1)
void sweep_kernel(const float* __restrict__ feats, const int* __restrict__ nbd,
                  const float* __restrict__ W_agg, const float* __restrict__ b_agg,
                  const float* __restrict__ W0,    const float* __restrict__ b0,
                  const __half* __restrict__ aggb, unsigned* __restrict__ nm2w) {
    extern __shared__ float sm[];
    float* As  = sm;                      // [32][68]  K-transposed A tile
    float* Bs  = As + 32 * 68;            // [32][256] (reused as agg2 fp16 staging)
    float* H1T = Bs + 32 * 256;           // [256][65] H1 tile col-major
    float* s_b = H1T + 256 * 65;          // b_agg
    int*  s_nbo = (int*)(s_b + 256);      // [64][16] owner-mapped neighbors

    const int tx = threadIdx.x, ty = threadIdx.y;
    const int tid = ty * 32 + tx;
    const int rowBase = blockIdx.x * 64;
    const int lr = tid >> 3, lk4 = tid & 7;
    const int bk = tid >> 6, bc4 = tid & 63;

    if (tid < 256) s_b[tid] = __ldg(&b_agg[tid]);
    for (int e = tid; e < 64 * DEG; e += 512) {
        int r = rowBase + (e >> 4);
        int o = -1;
        if (r < N_NODES) o = g_owner[__ldg(&nbd[r * DEG + (e & 15)])];
        s_nbo[e] = o;
    }
    const int myRow = rowBase + lr;
    const bool rowOk = (myRow < N_NODES);
    const int oSelf = rowOk ? g_owner[myRow] : -1;
    __syncthreads();

    // ---------------- phase C: H1 tile
    float acc[4][8];
#pragma unroll
    for (int i = 0; i < 4; ++i)
#pragma unroll
        for (int j = 0; j < 8; ++j) acc[i][j] = 0.f;

#pragma unroll 1
    for (int t = 0; t < 16; ++t) {
        const int kbase = t * 32;
        float4 v = make_float4(0.f, 0.f, 0.f, 0.f);
        if (rowOk) {
            if (t < 8) {                 // H0 half: feats[owner] or zeros
                if (oSelf >= 0)
                    v = *(const float4*)&feats[oSelf * 256 + kbase + lk4 * 4];
            } else {                     // nm1 half: max over neighbors, fp16 aggb
                const int col = (kbase - 256) + lk4 * 4;
                float4 rb = make_float4(fmaxf(s_b[col + 0], 0.f),
                                        fmaxf(s_b[col + 1], 0.f),
                                        fmaxf(s_b[col + 2], 0.f),
                                        fmaxf(s_b[col + 3], 0.f));
                float4 m = make_float4(-1e30f, -1e30f, -1e30f, -1e30f);
                const int* nbo = &s_nbo[lr * DEG];
#pragma unroll
                for (int d = 0; d < DEG; ++d) {
                    int o = nbo[d];
                    float4 w;
                    if (o >= 0) {
                        const __half2* p = (const __half2*)&aggb[o * 256 + col];
                        float2 f01 = __half22float2(__ldg(&p[0]));
                        float2 f23 = __half22float2(__ldg(&p[1]));
                        w = make_float4(f01.x, f01.y, f23.x, f23.y);
                    } else {
                        w = rb;          // agg of zero state = relu(b_agg)
                    }
                    m.x = fmaxf(m.x, w.x); m.y = fmaxf(m.y, w.y);
                    m.z = fmaxf(m.z, w.z); m.w = fmaxf(m.w, w.w);
                }
                v = m;
            }
        }
        As[(lk4 * 4 + 0) * 68 + lr] = v.x;
        As[(lk4 * 4 + 1) * 68 + lr] = v.y;
        As[(lk4 * 4 + 2) * 68 + lr] = v.z;
        As[(lk4 * 4 + 3) * 68 + lr] = v.w;
#pragma unroll
        for (int p = 0; p < 4; ++p) {
            int kk = bk + p * 8;
            *(float4*)&Bs[kk * 256 + bc4 * 4] =
                *(const float4*)&W0[(kbase + kk) * 256 + bc4 * 4];
        }
        __syncthreads();
#pragma unroll
        for (int kk = 0; kk < 32; ++kk) {
            float4 av = *(const float4*)&As[kk * 68 + ty * 4];
            float a[4] = {av.x, av.y, av.z, av.w};
            float b[8];
#pragma unroll
            for (int j = 0; j < 8; ++j) b[j] = Bs[kk * 256 + tx + 32 * j];
#pragma unroll
            for (int i = 0; i < 4; ++i)
#pragma unroll
                for (int j = 0; j < 8; ++j) acc[i][j] = fmaf(a[i], b[j], acc[i][j]);
        }
        __syncthreads();
    }

    {   // epilogue C -> H1T
        float bv[8];
#pragma unroll
        for (int j = 0; j < 8; ++j) bv[j] = __ldg(&b0[tx + 32 * j]);
#pragma unroll
        for (int i = 0; i < 4; ++i) {
            float v[8], ss = 0.f;
#pragma unroll
            for (int j = 0; j < 8; ++j) {
                v[j] = fmaxf(acc[i][j] + bv[j], 0.f);
                ss = fmaf(v[j], v[j], ss);
            }
#pragma unroll
            for (int off = 16; off >= 1; off >>= 1)
                ss += __shfl_xor_sync(0xffffffffu, ss, off);
            float inv = 1.f / fmaxf(sqrtf(ss), EPS);
#pragma unroll
            for (int j = 0; j < 8; ++j)
                H1T[(tx + 32 * j) * 65 + ty * 4 + i] = v[j] * inv;
        }
    }
    __syncthreads();

    // ---------------- phase D: agg2 tile
    float acc2[4][8];
#pragma unroll
    for (int i = 0; i < 4; ++i)
#pragma unroll
        for (int j = 0; j < 8; ++j) acc2[i][j] = 0.f;

#pragma unroll 1
    for (int t = 0; t < 8; ++t) {
        const int kbase = t * 32;
#pragma unroll
        for (int p = 0; p < 4; ++p) {
            int kk = bk + p * 8;
            *(float4*)&Bs[kk * 256 + bc4 * 4] =
                *(const float4*)&W_agg[(kbase + kk) * 256 + bc4 * 4];
        }
        __syncthreads();
#pragma unroll
        for (int kk = 0; kk < 32; ++kk) {
            const int kg = kbase + kk;
            float a[4];
#pragma unroll
            for (int i = 0; i < 4; ++i) a[i] = H1T[kg * 65 + ty * 4 + i];
            float b[8];
#pragma unroll
            for (int j = 0; j < 8; ++j) b[j] = Bs[kk * 256 + tx + 32 * j];
#pragma unroll
            for (int i = 0; i < 4; ++i)
#pragma unroll
                for (int j = 0; j < 8; ++j) acc2[i][j] = fmaf(a[i], b[j], acc2[i][j]);
        }
        __syncthreads();
    }

    // stage agg2 fp16 into Bs, then CSR scatter-max into nm2
    __half* stg = (__half*)Bs;
#pragma unroll
    for (int i = 0; i < 4; ++i) {
        int lrow = ty * 4 + i;
#pragma unroll
        for (int j = 0; j < 8; ++j)
            stg[lrow * 256 + tx + 32 * j] =
                __float2half_rn(fmaxf(acc2[i][j] + s_b[tx + 32 * j], 0.f));
    }
    __syncthreads();

    const unsigned* stw = (const unsigned*)Bs;   // [64][128] packed half2
    for (int rr = ty; rr < 64; rr += 16) {
        int r = rowBase + rr;
        if (r >= N_NODES) continue;
        int s = g_roff[r], e = g_roff[r + 1];
        for (int m = s; m < e; ++m) {
            int en = g_rlist[m];
            unsigned* dst = nm2w + en * 128;
#pragma unroll
            for (int w = 0; w < 4; ++w)
                atomic_max_half2(&dst[tx + 32 * w], stw[rr * 128 + tx + 32 * w]);
        }
    }
}

// ---------------------------------------------------------------------------
// final kernel (128 blocks, all co-resident at 1 block/SM):
//   pre-barrier : recompute H1 for its 64 batch rows -> smem;
//                 copy its own nm2 rows -> smem
//   grid barrier (manual, self-resetting)
//   post-barrier: out = normalize(relu([H1 | nm2] @ W1 + b1)) -> d_out
// ---------------------------------------------------------------------------
#define FINAL_SMEM ((32*68 + 32*256 + 256*65 + 256) * 4 + 64*256*2 + 64*DEG*4) // 145920

__global__ __launch_bounds__(512, 1)
void final_kernel(const int* __restrict__ node_idx, const float* __restrict__ feats,
                  const int* __restrict__ nbd,
                  const float* __restrict__ W0, const float* __restrict__ b0,
                  const float* __restrict__ W1, const float* __restrict__ b1,
                  const float* __restrict__ b_agg,
                  const __half* __restrict__ aggb, const unsigned* __restrict__ nm2w,
                  float* __restrict__ out) {
    extern __shared__ float sm[];
    float* As   = sm;                     // [32][68]
    float* Bs   = As + 32 * 68;           // [32][256]
    float* H1T  = Bs + 32 * 256;          // [256][65]
    float* s_b  = H1T + 256 * 65;         // b_agg
    __half* nm2T = (__half*)(s_b + 256);  // [64][256]
    int*  s_nbo = (int*)(nm2T + 64 * 256);// [64][16]

    const int tx = threadIdx.x, ty = threadIdx.y;
    const int tid = ty * 32 + tx;
    const int rowBase = blockIdx.x * 64;
    const int lr = tid >> 3, lk4 = tid & 7;
    const int bk = tid >> 6, bc4 = tid & 63;

    if (tid < 256) s_b[tid] = __ldg(&b_agg[tid]);
    for (int e = tid; e < 64 * DEG; e += 512) {
        int x = __ldg(&node_idx[rowBase + (e >> 4)]);
        s_nbo[e] = g_owner[__ldg(&nbd[x * DEG + (e & 15)])];
    }
    const int myX  = __ldg(&node_idx[rowBase + lr]);
    const int oSelf = g_owner[myX];
    __syncthreads();

    // phase C': H1 tile for batch rows (same math as sweep)
    float acc[4][8];
#pragma unroll
    for (int i = 0; i < 4; ++i)
#pragma unroll
        for (int j = 0; j < 8; ++j) acc[i][j] = 0.f;

#pragma unroll 1
    for (int t = 0; t < 16; ++t) {
        const int kbase = t * 32;
        float4 v = make_float4(0.f, 0.f, 0.f, 0.f);
        if (t < 8) {
            if (oSelf >= 0)
                v = *(const float4*)&feats[oSelf * 256 + kbase + lk4 * 4];
        } else {
            const int col = (kbase - 256) + lk4 * 4;
            float4 rb = make_float4(fmaxf(s_b[col + 0], 0.f),
                                    fmaxf(s_b[col + 1], 0.f),
                                    fmaxf(s_b[col + 2], 0.f),
                                    fmaxf(s_b[col + 3], 0.f));
            float4 m = make_float4(-1e30f, -1e30f, -1e30f, -1e30f);
            const int* nbo = &s_nbo[lr * DEG];
#pragma unroll
            for (int d = 0; d < DEG; ++d) {
                int o = nbo[d];
                float4 w;
                if (o >= 0) {
                    const __half2* p = (const __half2*)&aggb[o * 256 + col];
                    float2 f01 = __half22float2(__ldg(&p[0]));
                    float2 f23 = __half22float2(__ldg(&p[1]));
                    w = make_float4(f01.x, f01.y, f23.x, f23.y);
                } else {
                    w = rb;
                }
                m.x = fmaxf(m.x, w.x); m.y = fmaxf(m.y, w.y);
                m.z = fmaxf(m.z, w.z); m.w = fmaxf(m.w, w.w);
            }
            v = m;
        }
        As[(lk4 * 4 + 0) * 68 + lr] = v.x;
        As[(lk4 * 4 + 1) * 68 + lr] = v.y;
        As[(lk4 * 4 + 2) * 68 + lr] = v.z;
        As[(lk4 * 4 + 3) * 68 + lr] = v.w;
#pragma unroll
        for (int p = 0; p < 4; ++p) {
            int kk = bk + p * 8;
            *(float4*)&Bs[kk * 256 + bc4 * 4] =
                *(const float4*)&W0[(kbase + kk) * 256 + bc4 * 4];
        }
        __syncthreads();
#pragma unroll
        for (int kk = 0; kk < 32; ++kk) {
            float4 av = *(const float4*)&As[kk * 68 + ty * 4];
            float a[4] = {av.x, av.y, av.z, av.w};
            float b[8];
#pragma unroll
            for (int j = 0; j < 8; ++j) b[j] = Bs[kk * 256 + tx + 32 * j];
#pragma unroll
            for (int i = 0; i < 4; ++i)
#pragma unroll
                for (int j = 0; j < 8; ++j) acc[i][j] = fmaf(a[i], b[j], acc[i][j]);
        }
        __syncthreads();
    }

    {   // epilogue C' -> H1T
        float bv[8];
#pragma unroll
        for (int j = 0; j < 8; ++j) bv[j] = __ldg(&b0[tx + 32 * j]);
#pragma unroll
        for (int i = 0; i < 4; ++i) {
            float v[8], ss = 0.f;
#pragma unroll
            for (int j = 0; j < 8; ++j) {
                v[j] = fmaxf(acc[i][j] + bv[j], 0.f);
                ss = fmaf(v[j], v[j], ss);
            }
#pragma unroll
            for (int off = 16; off >= 1; off >>= 1)
                ss += __shfl_xor_sync(0xffffffffu, ss, off);
            float inv = 1.f / fmaxf(sqrtf(ss), EPS);
#pragma unroll
            for (int j = 0; j < 8; ++j)
                H1T[(tx + 32 * j) * 65 + ty * 4 + i] = v[j] * inv;
        }
    }

    // copy own nm2 rows to smem (pre-barrier)
    {
        unsigned* nm2Tw = (unsigned*)nm2T;
        for (int w = tid; w < 64 * 128; w += 512)
            nm2Tw[w] = __ldg(&nm2w[rowBase * 128 + w]);
    }
    __syncthreads();

    // ---- manual grid barrier (all 128 blocks co-resident; self-resetting) ----
    if (tid == 0) {
        unsigned phase = atomicAdd(&g_barPhase, 0u);
        unsigned t = atomicAdd(&g_barCount, 1u);
        if (t == gridDim.x - 1) {
            g_barCount = 0u;
            __threadfence();
            atomicAdd(&g_barPhase, 1u);
        } else {
            while (atomicAdd(&g_barPhase, 0u) == phase) { }
        }
    }
    __syncthreads();

    // phase D': out = normalize(relu([H1 | nm2] @ W1 + b1))
    float acc2[4][8];
#pragma unroll
    for (int i = 0; i < 4; ++i)
#pragma unroll
        for (int j = 0; j < 8; ++j) acc2[i][j] = 0.f;

#pragma unroll 1
    for (int t = 0; t < 16; ++t) {
        const int kbase = t * 32;
#pragma unroll
        for (int p = 0; p < 4; ++p) {
            int kk = bk + p * 8;
            *(float4*)&Bs[kk * 256 + bc4 * 4] =
                *(const float4*)&W1[(kbase + kk) * 256 + bc4 * 4];
        }
        __syncthreads();
#pragma unroll
        for (int kk = 0; kk < 32; ++kk) {
            const int kg = kbase + kk;
            float a[4];
            if (t < 8) {
#pragma unroll
                for (int i = 0; i < 4; ++i) a[i] = H1T[kg * 65 + ty * 4 + i];
            } else {
#pragma unroll
                for (int i = 0; i < 4; ++i)
                    a[i] = __half2float(nm2T[(ty * 4 + i) * 256 + (kg - 256)]);
            }
            float b[8];
#pragma unroll
            for (int j = 0; j < 8; ++j) b[j] = Bs[kk * 256 + tx + 32 * j];
#pragma unroll
            for (int i = 0; i < 4; ++i)
#pragma unroll
                for (int j = 0; j < 8; ++j) acc2[i][j] = fmaf(a[i], b[j], acc2[i][j]);
        }
        __syncthreads();
    }

    {   // epilogue D': bias + relu + normalize -> d_out
        float bv[8];
#pragma unroll
        for (int j = 0; j < 8; ++j) bv[j] = __ldg(&b1[tx + 32 * j]);
#pragma unroll
        for (int i = 0; i < 4; ++i) {
            float v[8], ss = 0.f;
#pragma unroll
            for (int j = 0; j < 8; ++j) {
                v[j] = fmaxf(acc2[i][j] + bv[j], 0.f);
                ss = fmaf(v[j], v[j], ss);
            }
#pragma unroll
            for (int off = 16; off >= 1; off >>= 1)
                ss += __shfl_xor_sync(0xffffffffu, ss, off);
            float inv = 1.f / fmaxf(sqrtf(ss), EPS);
            int r = rowBase + ty * 4 + i;
#pragma unroll
            for (int j = 0; j < 8; ++j) out[r * 256 + tx + 32 * j] = v[j] * inv;
        }
    }
}

// ---------------------------------------------------------------------------
// launch: node_idx, feats, nbd, W_agg, b_agg, W_lin, b_lin  -> out [B,256]
// ---------------------------------------------------------------------------
extern "C" void kernel_launch(void* const* d_in, const int* in_sizes, int n_in,
                              void* d_out, int out_size) {
    const int*   node_idx = (const int*)d_in[0];
    const float* feats    = (const float*)d_in[1];
    const int*   nbd      = (const int*)d_in[2];
    const float* W_agg    = (const float*)d_in[3];
    const float* b_agg    = (const float*)d_in[4];
    const float* W_lin    = (const float*)d_in[5];  // [2, 512, 256]
    const float* b_lin    = (const float*)d_in[6];  // [2, 256]

    // d_out layout: [0, 4.19MB) aggb fp16 ; [4.19MB, 8.39MB) nm2 packed half2
    __half*   aggb = (__half*)d_out;
    unsigned* nm2w = (unsigned*)((char*)d_out + AGGB_BYTES);
    float*    out  = (float*)d_out;
    int*      cnt  = (int*)d_out;    // setup-phase scratch (dead before aggb GEMM)

    cudaFuncSetAttribute(sweep_kernel,
                         cudaFuncAttributeMaxDynamicSharedMemorySize, SWEEP_SMEM);
    cudaFuncSetAttribute(final_kernel,
                         cudaFuncAttributeMaxDynamicSharedMemorySize, FINAL_SMEM);

    dim3 gblk(32, 16);
    const int gridN = (N_NODES + 63) / 64;   // 782
    const int gridB = BATCH / 64;            // 128

    init_kernel<<<(N_NODES + 255) / 256, 256>>>(cnt);
    owner_scatter_kernel<<<(BATCH + 255) / 256, 256>>>(node_idx);
    count_refs_kernel<<<NREF / 256, 256>>>(node_idx, nbd, cnt);
    scanA_kernel<<<SCANB, 1024>>>(cnt);
    scanB_kernel<<<1, 64>>>();
    scanC_kernel<<<SCANB, 1024>>>(cnt);
    fill_refs_kernel<<<NREF / 256, 256>>>(node_idx, nbd, cnt);

    // aggb = relu(feats @ W_agg + b_agg)  (fp16, overwrites cnt region)
    aggb_gemm_kernel<<<gridB, gblk>>>(feats, W_agg, b_agg, aggb);
    // nm2 accumulator = 0 (identity for max over relu values)
    zero_nm2_kernel<<<(BATCH * 128 / 4 + 255) / 256, 256>>>((float4*)nm2w);
    // fused sweep over all nodes: H1 -> agg2 -> scatter-max nm2
    sweep_kernel<<<gridN, gblk, SWEEP_SMEM>>>(
        feats, nbd, W_agg, b_agg, W_lin, b_lin, aggb, nm2w);
    // final: recompute batch H1, combine with nm2, write out (grid barrier inside)
    final_kernel<<<gridB, gblk, FINAL_SMEM>>>(
        node_idx, feats, nbd, W_lin, b_lin,
        W_lin + 512 * 256, b_lin + 256, b_agg, aggb, nm2w, out);
}